// round 1
// baseline (speedup 1.0000x reference)
#include <cuda_runtime.h>

// Problem constants
#define CIN   512
#define COUT  32
#define HW    56
#define KC    8      // Cin chunk per shared-memory stage
#define TH    8      // output tile height per CTA
#define TW    28     // output tile width per CTA
#define XROWS 10     // TH + 2 halo
#define XCOLS 32     // TW + 2 halo, padded to 32 floats (128B rows)
#define WSTR  34     // padded oc-stride for weight tile (even -> 8B aligned, 2-way max)
#define NTHREADS 224

__global__ __launch_bounds__(NTHREADS, 3)
void fused_bn_relu_conv3x3(
    const float* __restrict__ x,      // [N, CIN, 56, 56]
    const float* __restrict__ gamma,  // [CIN]
    const float* __restrict__ beta,   // [CIN]
    const float* __restrict__ rmean,  // [CIN]
    const float* __restrict__ rvar,   // [CIN]
    const float* __restrict__ cw,     // [COUT, CIN, 3, 3]
    float* __restrict__ out)          // [N, COUT, 56, 56]
{
    __shared__ __align__(16) float s_x[KC][XROWS][XCOLS];      // 10.24 KB
    __shared__ __align__(16) float s_w[KC * 9 * WSTR];         //  9.79 KB
    __shared__ float s_scale[CIN];                             //  2 KB
    __shared__ float s_shift[CIN];                             //  2 KB

    const int tid = threadIdx.x;
    const int n   = blockIdx.z;
    const int h0  = blockIdx.y * TH;
    const int w0  = blockIdx.x * TW;

    // thread decomposition: 4 oc-groups x 56 pixel-threads (8 rows x 7 quads)
    const int ocg = tid / 56;            // 0..3  -> oc base = ocg*8
    const int p   = tid % 56;
    const int ty  = p / 7;               // 0..7
    const int tx4 = (p % 7) * 4;         // 0,4,...,24

    // Precompute fused BN scale/shift for all channels once.
    for (int i = tid; i < CIN; i += NTHREADS) {
        float inv = rsqrtf(rvar[i] + 1e-5f);
        float sc  = gamma[i] * inv;
        s_scale[i] = sc;
        s_shift[i] = beta[i] - rmean[i] * sc;
    }
    __syncthreads();

    // Accumulators: [oc-pair j 0..3][pixel q 0..3] as packed f32x2
    unsigned long long acc[4][4];
#pragma unroll
    for (int j = 0; j < 4; j++)
#pragma unroll
        for (int q = 0; q < 4; q++) acc[j][q] = 0ull;

    const float* xn = x + (long long)n * CIN * HW * HW;

    for (int c0 = 0; c0 < CIN; c0 += KC) {
        // ---- stage x tile (with halo), fused BN + ReLU ----
        for (int i = tid; i < KC * XROWS * 30; i += NTHREADS) {
            int c   = i / (XROWS * 30);
            int rem = i % (XROWS * 30);
            int r   = rem / 30;
            int col = rem % 30;
            int gh = h0 - 1 + r;
            int gw = w0 - 1 + col;
            float v = 0.0f;
            if ((unsigned)gh < HW && (unsigned)gw < HW) {
                float xv = xn[(c0 + c) * (HW * HW) + gh * HW + gw];
                v = fmaxf(fmaf(xv, s_scale[c0 + c], s_shift[c0 + c]), 0.0f);
            }
            s_x[c][r][col] = v;
        }
        // ---- stage weights: s_w[(c*9+k)*WSTR + oc], GMEM-coalesced (k innermost) ----
        for (int i = tid; i < COUT * KC * 9; i += NTHREADS) {
            int oc  = i / (KC * 9);
            int rem = i % (KC * 9);          // rem = c*9 + k, contiguous in GMEM
            s_w[rem * WSTR + oc] = cw[oc * (CIN * 9) + c0 * 9 + rem];
        }
        __syncthreads();

        // ---- compute ----
#pragma unroll
        for (int c = 0; c < KC; c++) {
#pragma unroll
            for (int kh = 0; kh < 3; kh++) {
                const float* xr = &s_x[c][ty + kh][tx4];
                float4 x03 = *(const float4*)xr;        // 16B aligned
                float2 x45 = *(const float2*)(xr + 4);  // 8B aligned
                float xv[6] = {x03.x, x03.y, x03.z, x03.w, x45.x, x45.y};
#pragma unroll
                for (int kw = 0; kw < 3; kw++) {
                    const unsigned long long* wp = (const unsigned long long*)
                        &s_w[((c * 3 + kh) * 3 + kw) * WSTR + ocg * 8];
                    unsigned long long wv[4];
#pragma unroll
                    for (int j = 0; j < 4; j++) wv[j] = wp[j];  // LDS.64, broadcast
#pragma unroll
                    for (int q = 0; q < 4; q++) {
                        unsigned long long xx;
                        unsigned xu = __float_as_uint(xv[kw + q]);
                        asm("mov.b64 %0, {%1, %1};" : "=l"(xx) : "r"(xu));
#pragma unroll
                        for (int j = 0; j < 4; j++)
                            asm("fma.rn.f32x2 %0, %1, %2, %0;"
                                : "+l"(acc[j][q]) : "l"(xx), "l"(wv[j]));
                    }
                }
            }
        }
        __syncthreads();
    }

    // ---- epilogue: unpack and store [N, COUT, 56, 56] ----
    const int h = h0 + ty;
#pragma unroll
    for (int j = 0; j < 4; j++) {
        int oc0 = ocg * 8 + 2 * j;
        float* o0 = out + ((n * COUT + oc0) * (HW * HW)) + h * HW + w0 + tx4;
        float* o1 = o0 + HW * HW;
#pragma unroll
        for (int q = 0; q < 4; q++) {
            unsigned lo, hi;
            asm("mov.b64 {%0, %1}, %2;" : "=r"(lo), "=r"(hi) : "l"(acc[j][q]));
            o0[q] = __uint_as_float(lo);
            o1[q] = __uint_as_float(hi);
        }
    }
}

extern "C" void kernel_launch(void* const* d_in, const int* in_sizes, int n_in,
                              void* d_out, int out_size) {
    // metadata order: x_slice, out_map(unused), bn_weight, bn_bias,
    //                 running_mean, running_var, conv_weight, write_offset(unused)
    const float* x     = (const float*)d_in[0];
    const float* gamma = (const float*)d_in[2];
    const float* beta  = (const float*)d_in[3];
    const float* rmean = (const float*)d_in[4];
    const float* rvar  = (const float*)d_in[5];
    const float* cw    = (const float*)d_in[6];
    float* out = (float*)d_out;

    dim3 grid(HW / TW, HW / TH, 32);   // (2, 7, 32) = 448 CTAs
    fused_bn_relu_conv3x3<<<grid, NTHREADS>>>(x, gamma, beta, rmean, rvar, cw, out);
}

// round 2
// speedup vs baseline: 1.1576x; 1.1576x over previous
#include <cuda_runtime.h>

#define CIN     512
#define COUT    32
#define HW      56
#define PLANE   3136
#define KC      8
#define NCHUNK  (CIN / KC)          // 64
#define TH      8
#define TW      28
#define XROWS   10
#define XCOLS   32                  // 30 used + pad -> 128B rows
#define WSTR    34                  // padded oc-stride (even -> 8B aligned)
#define NTHREADS 224
#define XELEMS  (KC * XROWS * XCOLS)  // 2560
#define WELEMS  (KC * 9 * WSTR)       // 2448
#define XSTAGE  (KC * XROWS * 30)     // 2400
#define WSTAGE  (COUT * KC * 9)       // 2304

// BN+ReLU'd copy of x (scratch; device-global per harness rules)
__device__ float g_xbn[32 * CIN * PLANE + 8];

// ---------------- Kernel 1: BN + ReLU pre-pass (memory-bound) ----------------
__global__ void bn_relu_pre(const float* __restrict__ x,
                            const float* __restrict__ gamma,
                            const float* __restrict__ beta,
                            const float* __restrict__ rmean,
                            const float* __restrict__ rvar)
{
    int idx = blockIdx.x * blockDim.x + threadIdx.x;
    const int total4 = 32 * CIN * (PLANE / 4);   // 12,845,056 float4s
    if (idx >= total4) return;
    int c = (idx / (PLANE / 4)) & (CIN - 1);     // channel (uniform per float4)
    float inv = rsqrtf(__ldg(&rvar[c]) + 1e-5f);
    float sc  = __ldg(&gamma[c]) * inv;
    float sh  = fmaf(-__ldg(&rmean[c]), sc, __ldg(&beta[c]));
    float4 v = ((const float4*)x)[idx];
    v.x = fmaxf(fmaf(v.x, sc, sh), 0.0f);
    v.y = fmaxf(fmaf(v.y, sc, sh), 0.0f);
    v.z = fmaxf(fmaf(v.z, sc, sh), 0.0f);
    v.w = fmaxf(fmaf(v.w, sc, sh), 0.0f);
    ((float4*)g_xbn)[idx] = v;
}

// ---------------- Kernel 2: 3x3 conv, cp.async double-buffered, FFMA2 ----------------
__device__ __forceinline__ unsigned smem_u32(const void* p) {
    return (unsigned)__cvta_generic_to_shared(p);
}

__device__ __forceinline__ void stage_chunk(int k,
                                            const unsigned* xmeta, const unsigned* wmeta,
                                            const float* __restrict__ xbase,
                                            const float* __restrict__ wbase,
                                            unsigned sxb, unsigned swb)
{
    const float* xb = xbase + k * (KC * PLANE);
    const float* wb = wbase + k * (KC * 9);
#pragma unroll
    for (int s = 0; s < 11; s++) {
        unsigned m = xmeta[s];
        if (m & (1u << 28)) {
            unsigned dst = sxb + (m & 0xFFFu) * 4u;
            const float* src = xb + ((m >> 12) & 0x7FFFu);
            unsigned sz = (m & (1u << 27)) ? 4u : 0u;   // zfill halo / OOB
            asm volatile("cp.async.ca.shared.global [%0], [%1], 4, %2;\n"
                         :: "r"(dst), "l"(src), "r"(sz));
        }
        unsigned mw = wmeta[s];
        if (mw & (1u << 31)) {
            unsigned dst = swb + (mw & 0xFFFu) * 4u;
            const float* src = wb + ((mw >> 12) & 0x3FFFFu);
            asm volatile("cp.async.ca.shared.global [%0], [%1], 4;\n"
                         :: "r"(dst), "l"(src));
        }
    }
    asm volatile("cp.async.commit_group;\n" ::: "memory");
}

__device__ __forceinline__ void compute_chunk(const float* __restrict__ sx,
                                              const float* __restrict__ sw,
                                              int ty, int tx4, int ocg,
                                              unsigned long long acc[4][4])
{
#pragma unroll
    for (int c = 0; c < KC; c++) {
#pragma unroll
        for (int kh = 0; kh < 3; kh++) {
            const float* xr = sx + ((c * XROWS + ty + kh) * XCOLS + tx4);
            float4 a  = *(const float4*)xr;          // 16B aligned
            float2 b2 = *(const float2*)(xr + 4);
            float xv[6] = {a.x, a.y, a.z, a.w, b2.x, b2.y};
            unsigned long long xx[6];
#pragma unroll
            for (int t = 0; t < 6; t++) {
                unsigned u = __float_as_uint(xv[t]);
                asm("mov.b64 %0, {%1, %1};" : "=l"(xx[t]) : "r"(u));
            }
#pragma unroll
            for (int kw = 0; kw < 3; kw++) {
                const unsigned long long* wp = (const unsigned long long*)
                    (sw + ((c * 3 + kh) * 3 + kw) * WSTR + ocg * 8);
                unsigned long long wv0 = wp[0], wv1 = wp[1], wv2 = wp[2], wv3 = wp[3];
#pragma unroll
                for (int q = 0; q < 4; q++) {
                    asm("fma.rn.f32x2 %0, %1, %2, %0;" : "+l"(acc[0][q]) : "l"(xx[kw + q]), "l"(wv0));
                    asm("fma.rn.f32x2 %0, %1, %2, %0;" : "+l"(acc[1][q]) : "l"(xx[kw + q]), "l"(wv1));
                    asm("fma.rn.f32x2 %0, %1, %2, %0;" : "+l"(acc[2][q]) : "l"(xx[kw + q]), "l"(wv2));
                    asm("fma.rn.f32x2 %0, %1, %2, %0;" : "+l"(acc[3][q]) : "l"(xx[kw + q]), "l"(wv3));
                }
            }
        }
    }
}

__global__ __launch_bounds__(NTHREADS, 3)
void conv3x3_async(const float* __restrict__ cw, float* __restrict__ out)
{
    __shared__ __align__(16) float s_x[2][XELEMS];   // 20.5 KB
    __shared__ __align__(16) float s_w[2][WELEMS];   // 19.6 KB

    const int tid = threadIdx.x;
    const int n   = blockIdx.z;
    const int h0  = blockIdx.y * TH;
    const int w0  = blockIdx.x * TW;

    // thread map: ocg in low bits -> quads share x float4 (LDS broadcast),
    // 4 distinct weight addrs per warp land in distinct banks.
    const int ocg = tid & 3;
    const int pix = tid >> 2;          // 0..55
    const int ty  = pix / 7;           // 0..7
    const int tx4 = (pix % 7) * 4;     // 0..24

    // per-thread staging slot tables (chunk-invariant)
    unsigned xmeta[11], wmeta[11];
#pragma unroll
    for (int s = 0; s < 11; s++) {
        int i = tid + s * NTHREADS;
        // x slot
        unsigned ex = (i < XSTAGE) ? 1u : 0u;
        int c = i / 300, rem = i - c * 300;
        int r = rem / 30, col = rem - r * 30;
        int gh = h0 - 1 + r, gw = w0 - 1 + col;
        unsigned inb = (((unsigned)gh < HW) && ((unsigned)gw < HW)) ? 1u : 0u;
        int src = inb ? (c * PLANE + gh * HW + gw) : 0;
        int dst = (c * XROWS + r) * XCOLS + col;
        xmeta[s] = (unsigned)dst | ((unsigned)src << 12) | (inb << 27) | (ex << 28);
        // w slot
        unsigned exw = (i < WSTAGE) ? 1u : 0u;
        int oc = i / 72, remw = i - oc * 72;
        unsigned wsrc = (unsigned)(oc * (CIN * 9) + remw) & 0x3FFFFu;
        wmeta[s] = (unsigned)(remw * WSTR + oc) | (wsrc << 12) | (exw << 31);
    }

    const float* xbase = g_xbn + (size_t)n * CIN * PLANE;
    unsigned sxb0 = smem_u32(s_x[0]), sxb1 = smem_u32(s_x[1]);
    unsigned swb0 = smem_u32(s_w[0]), swb1 = smem_u32(s_w[1]);

    unsigned long long acc[4][4];
#pragma unroll
    for (int j = 0; j < 4; j++)
#pragma unroll
        for (int q = 0; q < 4; q++) acc[j][q] = 0ull;

    // prologue: 2 chunks in flight
    stage_chunk(0, xmeta, wmeta, xbase, cw, sxb0, swb0);
    stage_chunk(1, xmeta, wmeta, xbase, cw, sxb1, swb1);

#pragma unroll 1
    for (int k = 0; k < NCHUNK; k++) {
        if (k < NCHUNK - 1) asm volatile("cp.async.wait_group 1;\n" ::: "memory");
        else                asm volatile("cp.async.wait_group 0;\n" ::: "memory");
        __syncthreads();
        const int b = k & 1;
        compute_chunk(b ? s_x[1] : s_x[0], b ? s_w[1] : s_w[0], ty, tx4, ocg, acc);
        __syncthreads();
        if (k + 2 < NCHUNK)
            stage_chunk(k + 2, xmeta, wmeta, xbase, cw,
                        b ? sxb1 : sxb0, b ? swb1 : swb0);
    }

    // epilogue: unpack f32x2 (paired over oc) and store
    const int h = h0 + ty;
#pragma unroll
    for (int j = 0; j < 4; j++) {
        int oc0 = ocg * 8 + 2 * j;
        float* o0 = out + ((size_t)(n * COUT + oc0) * PLANE) + h * HW + w0 + tx4;
        float* o1 = o0 + PLANE;
#pragma unroll
        for (int q = 0; q < 4; q++) {
            unsigned lo, hi;
            asm("mov.b64 {%0, %1}, %2;" : "=r"(lo), "=r"(hi) : "l"(acc[j][q]));
            o0[q] = __uint_as_float(lo);
            o1[q] = __uint_as_float(hi);
        }
    }
}

extern "C" void kernel_launch(void* const* d_in, const int* in_sizes, int n_in,
                              void* d_out, int out_size) {
    // inputs: x_slice, out_map(unused), bn_weight, bn_bias, running_mean,
    //         running_var, conv_weight, write_offset(unused)
    const float* x     = (const float*)d_in[0];
    const float* gamma = (const float*)d_in[2];
    const float* beta  = (const float*)d_in[3];
    const float* rmean = (const float*)d_in[4];
    const float* rvar  = (const float*)d_in[5];
    const float* cw    = (const float*)d_in[6];
    float* out = (float*)d_out;

    const int total4 = 32 * CIN * (PLANE / 4);
    bn_relu_pre<<<(total4 + 255) / 256, 256>>>(x, gamma, beta, rmean, rvar);

    dim3 grid(HW / TW, HW / TH, 32);   // (2, 7, 32) = 448 CTAs
    conv3x3_async<<<grid, NTHREADS>>>(cw, out);
}

// round 3
// speedup vs baseline: 1.3978x; 1.2075x over previous
#include <cuda_runtime.h>

#define CIN     512
#define COUT    32
#define HW      56
#define PLANE   3136
#define HPAD    58
#define WPAD    64
#define CHPAD   (HPAD * WPAD)        // 3712 floats per padded channel
#define KC      8
#define NCHUNK  (CIN / KC)           // 64
#define TH      8
#define TW      28
#define XROWS   10
#define XCOLS   32
#define NTHREADS 224
#define XELEMS  (KC * XROWS * XCOLS) // 2560 floats
#define WELEMS  (KC * 9 * COUT)      // 2304 floats
#define XF4     (XELEMS / 4)         // 640 16B ops
#define WF4     (WELEMS / 4)         // 576 16B ops

// scratch (device globals per harness rules)
__device__ float g_xpad[32 * CIN * CHPAD];       // BN+ReLU'd, zero-padded halo
__device__ float g_wt[CIN * 9 * COUT];           // weights as [c][kh][kw][oc]

// ---------------- Kernel 1: BN+ReLU into padded layout ----------------
__global__ __launch_bounds__(256) void bn_relu_pad(
    const float* __restrict__ x, const float* __restrict__ gamma,
    const float* __restrict__ beta, const float* __restrict__ rmean,
    const float* __restrict__ rvar)
{
    __shared__ float sp[PLANE];
    const int id  = blockIdx.x;          // plane id = n*512 + c
    const int c   = id & (CIN - 1);
    const int tid = threadIdx.x;

    float inv = rsqrtf(__ldg(&rvar[c]) + 1e-5f);
    float sc  = __ldg(&gamma[c]) * inv;
    float sh  = fmaf(-__ldg(&rmean[c]), sc, __ldg(&beta[c]));

    const float4* src = (const float4*)(x + (size_t)id * PLANE);
    for (int i = tid; i < PLANE / 4; i += 256) {
        float4 v = src[i];
        v.x = fmaxf(fmaf(v.x, sc, sh), 0.0f);
        v.y = fmaxf(fmaf(v.y, sc, sh), 0.0f);
        v.z = fmaxf(fmaf(v.z, sc, sh), 0.0f);
        v.w = fmaxf(fmaf(v.w, sc, sh), 0.0f);
        ((float4*)sp)[i] = v;
    }
    __syncthreads();

    float4* dst = (float4*)(g_xpad + (size_t)id * CHPAD);
    for (int i = tid; i < HPAD * (WPAD / 4); i += 256) {
        int hp = i >> 4, v4 = i & 15;
        float4 o = make_float4(0.f, 0.f, 0.f, 0.f);
        if (hp >= 1 && hp <= HW) {
            const float* row = sp + (hp - 1) * HW;
            int pc = v4 * 4;
            float t[4];
#pragma unroll
            for (int j = 0; j < 4; j++) {
                int p = pc + j;
                t[j] = (p >= 1 && p <= HW) ? row[p - 1] : 0.0f;
            }
            o = make_float4(t[0], t[1], t[2], t[3]);
        }
        dst[i] = o;
    }
}

// ---------------- Kernel 2: weight transpose [oc][c][k] -> [c][k][oc] ----------------
__global__ __launch_bounds__(256) void wt_transpose(const float* __restrict__ cw)
{
    int idx = blockIdx.x * 256 + threadIdx.x;
    if (idx >= CIN * 9 * COUT) return;
    int ck = idx >> 5, oc = idx & 31;
    g_wt[idx] = cw[oc * (CIN * 9) + ck];
}

// ---------------- Kernel 3: conv 3x3, 16B cp.async double-buffered, FFMA2 ----------------
__device__ __forceinline__ unsigned smem_u32(const void* p) {
    return (unsigned)__cvta_generic_to_shared(p);
}

__global__ __launch_bounds__(NTHREADS, 4)
void conv3x3_async(float* __restrict__ out)
{
    __shared__ __align__(16) float s_x[2][XELEMS];   // 20.5 KB
    __shared__ __align__(16) float s_w[2][WELEMS];   // 18.4 KB

    const int tid = threadIdx.x;
    const int n   = blockIdx.z;
    const int h0  = blockIdx.y * TH;
    const int w0  = blockIdx.x * TW;

    const int ocg = tid & 3;           // quads share x float4 (LDS broadcast)
    const int pix = tid >> 2;
    const int ty  = pix / 7;
    const int tx4 = (pix % 7) * 4;

    // chunk-invariant staging offsets (3 slots, float units / byte units)
    unsigned xsrc[3], xdst[3];
#pragma unroll
    for (int t = 0; t < 3; t++) {
        int s = tid + t * NTHREADS;            // < XF4 except slot2 when tid>=192
        int c = s / 80, rem = s % 80;
        int r = rem / 8, v = rem % 8;
        xsrc[t] = c * CHPAD + (h0 + r) * WPAD + w0 + v * 4;
        xdst[t] = ((c * XROWS + r) * XCOLS + v * 4) * 4u;
    }

    const float* xplane = g_xpad + (size_t)n * CIN * CHPAD;
    unsigned sxb[2] = { smem_u32(s_x[0]), smem_u32(s_x[1]) };
    unsigned swb[2] = { smem_u32(s_w[0]), smem_u32(s_w[1]) };

    unsigned long long acc[4][4];
#pragma unroll
    for (int j = 0; j < 4; j++)
#pragma unroll
        for (int q = 0; q < 4; q++) acc[j][q] = 0ull;

    // ---- staging lambda ----
    auto stage = [&](int k, int b) {
        const float* xb = xplane + (size_t)k * KC * CHPAD;
        const float* wb = g_wt + k * WELEMS;
#pragma unroll
        for (int t = 0; t < 3; t++) {
            if (t < 2 || tid < XF4 - 2 * NTHREADS) {
                asm volatile("cp.async.cg.shared.global [%0], [%1], 16;\n"
                             :: "r"(sxb[b] + xdst[t]), "l"(xb + xsrc[t]));
            }
        }
#pragma unroll
        for (int t = 0; t < 3; t++) {
            int s = tid + t * NTHREADS;
            if (t < 2 || tid < WF4 - 2 * NTHREADS) {
                asm volatile("cp.async.cg.shared.global [%0], [%1], 16;\n"
                             :: "r"(swb[b] + (unsigned)s * 16u), "l"(wb + s * 4));
            }
        }
        asm volatile("cp.async.commit_group;\n" ::: "memory");
    };

    stage(0, 0);
    stage(1, 1);

#pragma unroll 1
    for (int k = 0; k < NCHUNK; k++) {
        if (k < NCHUNK - 1) asm volatile("cp.async.wait_group 1;\n" ::: "memory");
        else                asm volatile("cp.async.wait_group 0;\n" ::: "memory");
        __syncthreads();
        const int b = k & 1;
        const float* sx = s_x[b];
        const float* sw = s_w[b];
#pragma unroll
        for (int c = 0; c < KC; c++) {
#pragma unroll
            for (int kh = 0; kh < 3; kh++) {
                const float* xr = sx + ((c * XROWS + ty + kh) * XCOLS + tx4);
                float4 a  = *(const float4*)xr;
                float2 b2 = *(const float2*)(xr + 4);
                float xv[6] = {a.x, a.y, a.z, a.w, b2.x, b2.y};
                unsigned long long xx[6];
#pragma unroll
                for (int t = 0; t < 6; t++) {
                    unsigned u = __float_as_uint(xv[t]);
                    asm("mov.b64 %0, {%1, %1};" : "=l"(xx[t]) : "r"(u));
                }
#pragma unroll
                for (int kw = 0; kw < 3; kw++) {
                    const unsigned long long* wp = (const unsigned long long*)
                        (sw + ((c * 3 + kh) * 3 + kw) * COUT + ocg * 8);
                    unsigned long long wv0 = wp[0], wv1 = wp[1], wv2 = wp[2], wv3 = wp[3];
#pragma unroll
                    for (int q = 0; q < 4; q++) {
                        asm("fma.rn.f32x2 %0, %1, %2, %0;" : "+l"(acc[0][q]) : "l"(xx[kw + q]), "l"(wv0));
                        asm("fma.rn.f32x2 %0, %1, %2, %0;" : "+l"(acc[1][q]) : "l"(xx[kw + q]), "l"(wv1));
                        asm("fma.rn.f32x2 %0, %1, %2, %0;" : "+l"(acc[2][q]) : "l"(xx[kw + q]), "l"(wv2));
                        asm("fma.rn.f32x2 %0, %1, %2, %0;" : "+l"(acc[3][q]) : "l"(xx[kw + q]), "l"(wv3));
                    }
                }
            }
        }
        __syncthreads();
        if (k + 2 < NCHUNK) stage(k + 2, b);
    }

    // ---- epilogue ----
    const int h = h0 + ty;
#pragma unroll
    for (int j = 0; j < 4; j++) {
        int oc0 = ocg * 8 + 2 * j;
        float* o0 = out + ((size_t)(n * COUT + oc0) * PLANE) + h * HW + w0 + tx4;
        float* o1 = o0 + PLANE;
#pragma unroll
        for (int q = 0; q < 4; q++) {
            unsigned lo, hi;
            asm("mov.b64 {%0, %1}, %2;" : "=r"(lo), "=r"(hi) : "l"(acc[j][q]));
            o0[q] = __uint_as_float(lo);
            o1[q] = __uint_as_float(hi);
        }
    }
}

extern "C" void kernel_launch(void* const* d_in, const int* in_sizes, int n_in,
                              void* d_out, int out_size) {
    // inputs: x_slice, out_map(unused), bn_weight, bn_bias, running_mean,
    //         running_var, conv_weight, write_offset(unused)
    const float* x     = (const float*)d_in[0];
    const float* gamma = (const float*)d_in[2];
    const float* beta  = (const float*)d_in[3];
    const float* rmean = (const float*)d_in[4];
    const float* rvar  = (const float*)d_in[5];
    const float* cw    = (const float*)d_in[6];
    float* out = (float*)d_out;

    bn_relu_pad<<<32 * CIN, 256>>>(x, gamma, beta, rmean, rvar);
    wt_transpose<<<(CIN * 9 * COUT + 255) / 256, 256>>>(cw);

    dim3 grid(HW / TW, HW / TH, 32);   // (2, 7, 32) = 448 CTAs
    conv3x3_async<<<grid, NTHREADS>>>(out);
}